// round 11
// baseline (speedup 1.0000x reference)
#include <cuda_runtime.h>
#include <math.h>

#define NLEV 16
#define MAX_SIZE (1u << 19)
#define P1 2654435761u
#define P2 805459861u

#define NPTS_MAX 2097152
#define KEY_BITS_DIM 6                   // res-64 Morton key
#define NBINS (1u << (3 * KEY_BITS_DIM)) // 262144 bins, ~8 pts/bin
#define SCAN_BLK 2048
#define NSCANBLKS (NBINS / SCAN_BLK)     // 128

struct LP {
    float    res[NLEV];
    unsigned mask[NLEV];
};

// Static scratch (allocation-free rule: __device__ globals)
__device__ unsigned d_hist[NBINS];      // becomes intra-block exclusive scan
__device__ unsigned d_bsums[NSCANBLKS]; // exclusive scan of block sums
__device__ unsigned d_perm[NPTS_MAX];   // sorted slot -> original point index
__device__ unsigned d_keys[NPTS_MAX];   // cached morton key per point
__device__ unsigned d_rank[NPTS_MAX];   // within-bin rank from hist pass

// ---------------- Morton key (6 bits/dim -> 18-bit key) ----------------
__device__ __forceinline__ unsigned expand_bits(unsigned v)
{
    v = (v | (v << 16)) & 0x030000FFu;
    v = (v | (v << 8))  & 0x0300F00Fu;
    v = (v | (v << 4))  & 0x030C30C3u;
    v = (v | (v << 2))  & 0x09249249u;
    return v;
}
__device__ __forceinline__ unsigned morton_key(float px, float py, float pz)
{
    unsigned ix = min(63u, (unsigned)(px * 64.0f));
    unsigned iy = min(63u, (unsigned)(py * 64.0f));
    unsigned iz = min(63u, (unsigned)(pz * 64.0f));
    return expand_bits(ix) | (expand_bits(iy) << 1) | (expand_bits(iz) << 2);
}

// ---------------- Sort pipeline ----------------
// hist also records each point's key and its within-bin rank (atomic return),
// so the scatter pass needs no atomics at all.
__global__ void k_hist(const float* __restrict__ x, int n)
{
    int i = blockIdx.x * blockDim.x + threadIdx.x;
    if (i >= n) return;
    unsigned k = morton_key(x[3 * i], x[3 * i + 1], x[3 * i + 2]);
    d_keys[i] = k;
    d_rank[i] = atomicAdd(&d_hist[k], 1u);
}

__global__ void __launch_bounds__(1024) k_scan1()
{
    __shared__ unsigned s[SCAN_BLK];
    const int t = threadIdx.x;
    const unsigned base = blockIdx.x * SCAN_BLK;
    s[t] = d_hist[base + t];
    s[t + 1024] = d_hist[base + t + 1024];
    int offset = 1;
    for (int d = SCAN_BLK >> 1; d > 0; d >>= 1) {
        __syncthreads();
        if (t < d) {
            int ai = offset * (2 * t + 1) - 1;
            int bi = offset * (2 * t + 2) - 1;
            s[bi] += s[ai];
        }
        offset <<= 1;
    }
    if (t == 0) { d_bsums[blockIdx.x] = s[SCAN_BLK - 1]; s[SCAN_BLK - 1] = 0; }
    for (int d = 1; d < SCAN_BLK; d <<= 1) {
        offset >>= 1;
        __syncthreads();
        if (t < d) {
            int ai = offset * (2 * t + 1) - 1;
            int bi = offset * (2 * t + 2) - 1;
            unsigned tm = s[ai]; s[ai] = s[bi]; s[bi] += tm;
        }
    }
    __syncthreads();
    d_hist[base + t] = s[t];
    d_hist[base + t + 1024] = s[t + 1024];
}

__global__ void __launch_bounds__(128) k_scan2()
{
    __shared__ unsigned s[NSCANBLKS];
    const int t = threadIdx.x;
    s[t] = d_bsums[t];
    __syncthreads();
    unsigned v = s[t];
    for (int d = 1; d < NSCANBLKS; d <<= 1) {
        unsigned add = (t >= d) ? s[t - d] : 0u;
        __syncthreads();
        v += add;
        s[t] = v;
        __syncthreads();
    }
    d_bsums[t] = (t == 0) ? 0u : s[t - 1];
}

// Atomic-free scatter: slot = local_scan[k] + block_prefix + rank.
__global__ void k_scatter(int n)
{
    int i = blockIdx.x * blockDim.x + threadIdx.x;
    if (i >= n) return;
    unsigned k = d_keys[i];
    unsigned p = d_hist[k] + d_bsums[k >> 11] + d_rank[i];
    d_perm[p] = (unsigned)i;
}

// ---------------- Main encode: 2 lanes/point, 16 points/warp ----------------
// Lane p handles the 4 corners with by = p. The bx=0/1 pair is fetched with a
// single aligned float4 load when ix is even (hash indices differ by XOR 1 ->
// one aligned float2-pair); the bx=1 LDG.64 is predicated on ix odd.
__global__ void __launch_bounds__(256)
hashgrid_kernel(const float* __restrict__ x,
                const float* __restrict__ tables,
                float* __restrict__ out,
                LP lp, int n)
{
    const int lane   = threadIdx.x & 31;
    const int warpid = (blockIdx.x * (blockDim.x >> 5)) + (threadIdx.x >> 5);
    const int ptraw  = warpid * 16 + (lane >> 1);
    const bool valid = ptraw < n;
    const int pt     = valid ? ptraw : (n - 1);   // clamp; lanes stay converged
    const unsigned p = lane & 1;                  // by for this lane

    const unsigned oidx = __ldg(&d_perm[pt]);
    const float px = __ldg(&x[3 * oidx + 0]);
    const float py = __ldg(&x[3 * oidx + 1]);
    const float pz = __ldg(&x[3 * oidx + 2]);

    // Lane p keeps levels [8p, 8p+8): 8 float2 = 4 float4.
    float rf[16];

#pragma unroll
    for (int l = 0; l < NLEV; ++l) {
        const float    res  = lp.res[l];
        const unsigned mask = lp.mask[l];
        const float2* __restrict__ tbl =
            reinterpret_cast<const float2*>(tables) + (size_t)l * MAX_SIZE;

        const float xs = px * res, ys = py * res, zs = pz * res;
        const float fx = floorf(xs), fy = floorf(ys), fz = floorf(zs);

        const unsigned ix = (unsigned)fx;
        const unsigned iy = (unsigned)fy + p;
        const unsigned iz = (unsigned)fz;
        const bool ix_even = (ix & 1u) == 0u;     // then hb == ha ^ 1

        const float xf = xs - fx, yf = ys - fy, zf = zs - fz;
        const float wx0 = 1.0f - xf, wx1 = xf;
        const float wy  = p ? yf : (1.0f - yf);
        const float w0  = wy * (1.0f - zf);   // bz = 0
        const float w1  = wy * zf;            // bz = 1

        const unsigned hy  = iy * P1;
        const unsigned hz0 = iz * P2;
        const unsigned hz1 = hz0 + P2;

        const unsigned ha0 = (ix       ^ hy ^ hz0) & mask;  // bx=0, bz=0
        const unsigned hb0 = ((ix + 1) ^ hy ^ hz0) & mask;  // bx=1, bz=0
        const unsigned ha1 = (ix       ^ hy ^ hz1) & mask;  // bx=0, bz=1
        const unsigned hb1 = ((ix + 1) ^ hy ^ hz1) & mask;  // bx=1, bz=1

        // Aligned float4 covering {ha & ~1, ha | 1}: always contains fa,
        // and contains fb exactly when ix is even.
        const float4 q0 = __ldg(reinterpret_cast<const float4*>(tbl + (ha0 & ~1u)));
        const float4 q1 = __ldg(reinterpret_cast<const float4*>(tbl + (ha1 & ~1u)));

        const float2 fa0 = (ha0 & 1u) ? make_float2(q0.z, q0.w) : make_float2(q0.x, q0.y);
        const float2 pb0 = (ha0 & 1u) ? make_float2(q0.x, q0.y) : make_float2(q0.z, q0.w);
        const float2 fa1 = (ha1 & 1u) ? make_float2(q1.z, q1.w) : make_float2(q1.x, q1.y);
        const float2 pb1 = (ha1 & 1u) ? make_float2(q1.x, q1.y) : make_float2(q1.z, q1.w);

        float2 fb0, fb1;
        if (ix_even) {
            fb0 = pb0;
            fb1 = pb1;
        } else {
            fb0 = __ldg(&tbl[hb0]);
            fb1 = __ldg(&tbl[hb1]);
        }

        const float wa0 = w0 * wx0, wb0 = w0 * wx1;
        const float wa1 = w1 * wx0, wb1 = w1 * wx1;

        float vx = wa0 * fa0.x;
        float vy = wa0 * fa0.y;
        vx = fmaf(wb0, fb0.x, vx);
        vy = fmaf(wb0, fb0.y, vy);
        vx = fmaf(wa1, fa1.x, vx);
        vy = fmaf(wa1, fa1.y, vy);
        vx = fmaf(wb1, fb1.x, vx);
        vy = fmaf(wb1, fb1.y, vy);

        // sum the two y-halves
        vx += __shfl_xor_sync(0xffffffffu, vx, 1);
        vy += __shfl_xor_sync(0xffffffffu, vy, 1);

        // lane p stashes levels 8p..8p+7
        if ((l >> 3) == (int)p) {
            rf[2 * (l & 7) + 0] = vx;
            rf[2 * (l & 7) + 1] = vy;
        }
    }

    if (valid) {
        float4* o = reinterpret_cast<float4*>(out + (size_t)oidx * 32) + 4 * p;
        o[0] = make_float4(rf[0],  rf[1],  rf[2],  rf[3]);
        o[1] = make_float4(rf[4],  rf[5],  rf[6],  rf[7]);
        o[2] = make_float4(rf[8],  rf[9],  rf[10], rf[11]);
        o[3] = make_float4(rf[12], rf[13], rf[14], rf[15]);
    }
}

extern "C" void kernel_launch(void* const* d_in, const int* in_sizes, int n_in,
                              void* d_out, int out_size)
{
    const float* x      = (const float*)d_in[0];
    const float* tables = (const float*)d_in[1];
    float*       out    = (float*)d_out;
    const int    n      = in_sizes[0] / 3;

    // Replicate the reference's level-resolution math EXACTLY in double precision.
    LP lp;
    const double b = exp((log(512.0) - log(16.0)) / 15.0);
    for (int l = 0; l < NLEV; ++l) {
        const double r   = floor(16.0 * pow(b, (double)l));
        const long   res = (long)r;
        long sz = res * res * res;
        if (sz > (1L << 19)) sz = (1L << 19);
        long p = 1;
        while (p < sz) p <<= 1;
        lp.res[l]  = (float)r;
        lp.mask[l] = (unsigned)(p - 1);
    }

    static void* hist_ptr = nullptr;
    if (!hist_ptr) cudaGetSymbolAddress(&hist_ptr, d_hist);

    // 1) zero histogram (1 MB)
    cudaMemsetAsync(hist_ptr, 0, NBINS * sizeof(unsigned), 0);

    // 2) histogram; cache key + within-bin rank per point
    k_hist<<<(n + 255) / 256, 256>>>(x, n);

    // 3) two-level exclusive scan
    k_scan1<<<NSCANBLKS, 1024>>>();
    k_scan2<<<1, 128>>>();

    // 4) atomic-free scatter of permutation indices
    k_scatter<<<(n + 255) / 256, 256>>>(n);

    // 5) encode: 16 points per warp, 128 points per 256-thread block
    const int threads = 256;
    const int pts_per_block = (threads / 32) * 16;
    const int blocks = (n + pts_per_block - 1) / pts_per_block;
    hashgrid_kernel<<<blocks, threads>>>(x, tables, out, lp, n);
}

// round 12
// speedup vs baseline: 1.2093x; 1.2093x over previous
#include <cuda_runtime.h>
#include <math.h>

#define NLEV 16
#define MAX_SIZE (1u << 19)
#define P1 2654435761u
#define P2 805459861u

#define NPTS_MAX 2097152
#define KEY_BITS_DIM 6                   // res-64 Morton key
#define NBINS (1u << (3 * KEY_BITS_DIM)) // 262144 bins, ~8 pts/bin
#define SCAN_BLK 2048
#define NSCANBLKS (NBINS / SCAN_BLK)     // 128

struct LP {
    float    res[NLEV];
    unsigned mask[NLEV];
};

// Static scratch (allocation-free rule: __device__ globals)
__device__ unsigned d_hist[NBINS];      // becomes intra-block exclusive scan
__device__ unsigned d_bsums[NSCANBLKS]; // exclusive scan of block sums
__device__ unsigned d_perm[NPTS_MAX];   // sorted slot -> original point index
__device__ unsigned d_keys[NPTS_MAX];   // cached morton key per point
__device__ unsigned d_rank[NPTS_MAX];   // within-bin rank from hist pass

// ---------------- Morton key (6 bits/dim -> 18-bit key) ----------------
__device__ __forceinline__ unsigned expand_bits(unsigned v)
{
    v = (v | (v << 16)) & 0x030000FFu;
    v = (v | (v << 8))  & 0x0300F00Fu;
    v = (v | (v << 4))  & 0x030C30C3u;
    v = (v | (v << 2))  & 0x09249249u;
    return v;
}
__device__ __forceinline__ unsigned morton_key(float px, float py, float pz)
{
    unsigned ix = min(63u, (unsigned)(px * 64.0f));
    unsigned iy = min(63u, (unsigned)(py * 64.0f));
    unsigned iz = min(63u, (unsigned)(pz * 64.0f));
    return expand_bits(ix) | (expand_bits(iy) << 1) | (expand_bits(iz) << 2);
}

// ---------------- Sort pipeline ----------------
__global__ void k_hist(const float* __restrict__ x, int n)
{
    int i = blockIdx.x * blockDim.x + threadIdx.x;
    if (i >= n) return;
    unsigned k = morton_key(x[3 * i], x[3 * i + 1], x[3 * i + 2]);
    d_keys[i] = k;
    d_rank[i] = atomicAdd(&d_hist[k], 1u);
}

__global__ void __launch_bounds__(1024) k_scan1()
{
    __shared__ unsigned s[SCAN_BLK];
    const int t = threadIdx.x;
    const unsigned base = blockIdx.x * SCAN_BLK;
    s[t] = d_hist[base + t];
    s[t + 1024] = d_hist[base + t + 1024];
    int offset = 1;
    for (int d = SCAN_BLK >> 1; d > 0; d >>= 1) {
        __syncthreads();
        if (t < d) {
            int ai = offset * (2 * t + 1) - 1;
            int bi = offset * (2 * t + 2) - 1;
            s[bi] += s[ai];
        }
        offset <<= 1;
    }
    if (t == 0) { d_bsums[blockIdx.x] = s[SCAN_BLK - 1]; s[SCAN_BLK - 1] = 0; }
    for (int d = 1; d < SCAN_BLK; d <<= 1) {
        offset >>= 1;
        __syncthreads();
        if (t < d) {
            int ai = offset * (2 * t + 1) - 1;
            int bi = offset * (2 * t + 2) - 1;
            unsigned tm = s[ai]; s[ai] = s[bi]; s[bi] += tm;
        }
    }
    __syncthreads();
    d_hist[base + t] = s[t];
    d_hist[base + t + 1024] = s[t + 1024];
}

__global__ void __launch_bounds__(128) k_scan2()
{
    __shared__ unsigned s[NSCANBLKS];
    const int t = threadIdx.x;
    s[t] = d_bsums[t];
    __syncthreads();
    unsigned v = s[t];
    for (int d = 1; d < NSCANBLKS; d <<= 1) {
        unsigned add = (t >= d) ? s[t - d] : 0u;
        __syncthreads();
        v += add;
        s[t] = v;
        __syncthreads();
    }
    d_bsums[t] = (t == 0) ? 0u : s[t - 1];
}

// Atomic-free scatter: slot = local_scan[k] + block_prefix + rank.
__global__ void k_scatter(int n)
{
    int i = blockIdx.x * blockDim.x + threadIdx.x;
    if (i >= n) return;
    unsigned k = d_keys[i];
    unsigned p = d_hist[k] + d_bsums[k >> 11] + d_rank[i];
    d_perm[p] = (unsigned)i;
}

// ---------------- Main encode: 2 lanes/point, 16 points/warp, lane = bx ----------------
// Lane p handles the 4 corners with bx = p (by,bz unrolled in-lane). The two
// lanes of a point load hash indices differing by XOR(ix^(ix+1)) inside the
// SAME LDG instruction -> same 128B line 15/16 of the time -> the x-pair
// wavefront merges in hardware. No divergence, no extra instructions.
__global__ void __launch_bounds__(256)
hashgrid_kernel(const float* __restrict__ x,
                const float* __restrict__ tables,
                float* __restrict__ out,
                LP lp, int n)
{
    const int lane   = threadIdx.x & 31;
    const int warpid = (blockIdx.x * (blockDim.x >> 5)) + (threadIdx.x >> 5);
    const int ptraw  = warpid * 16 + (lane >> 1);
    const bool valid = ptraw < n;
    const int pt     = valid ? ptraw : (n - 1);   // clamp; lanes stay converged
    const unsigned p = lane & 1;                  // bx for this lane

    const unsigned oidx = __ldg(&d_perm[pt]);
    const float px = __ldg(&x[3 * oidx + 0]);
    const float py = __ldg(&x[3 * oidx + 1]);
    const float pz = __ldg(&x[3 * oidx + 2]);

    // Lane p keeps levels [8p, 8p+8): 8 float2 = 4 float4.
    float rf[16];

#pragma unroll
    for (int l = 0; l < NLEV; ++l) {
        const float    res  = lp.res[l];
        const unsigned mask = lp.mask[l];
        const float2* __restrict__ tbl =
            reinterpret_cast<const float2*>(tables) + (size_t)l * MAX_SIZE;

        const float xs = px * res, ys = py * res, zs = pz * res;
        const float fx = floorf(xs), fy = floorf(ys), fz = floorf(zs);

        const unsigned ix = (unsigned)fx + p;
        const unsigned iy = (unsigned)fy;
        const unsigned iz = (unsigned)fz;

        const float xf = xs - fx, yf = ys - fy, zf = zs - fz;
        const float wx   = p ? xf : (1.0f - xf);
        const float wy0  = 1.0f - yf, wy1 = yf;
        const float wz0  = 1.0f - zf, wz1 = zf;
        const float w00  = wy0 * wz0;
        const float w10  = wy1 * wz0;
        const float w01  = wy0 * wz1;
        const float w11  = wy1 * wz1;

        const unsigned hy0 = iy * P1;
        const unsigned hy1 = hy0 + P1;
        const unsigned hz0 = iz * P2;
        const unsigned hz1 = hz0 + P2;

        const unsigned h00 = (ix ^ hy0 ^ hz0) & mask;
        const unsigned h10 = (ix ^ hy1 ^ hz0) & mask;
        const unsigned h01 = (ix ^ hy0 ^ hz1) & mask;
        const unsigned h11 = (ix ^ hy1 ^ hz1) & mask;

        const float2 f00 = __ldg(&tbl[h00]);
        const float2 f10 = __ldg(&tbl[h10]);
        const float2 f01 = __ldg(&tbl[h01]);
        const float2 f11 = __ldg(&tbl[h11]);

        // accumulate over (by,bz), then scale once by wx
        float ax = w00 * f00.x;
        float ay = w00 * f00.y;
        ax = fmaf(w10, f10.x, ax);
        ay = fmaf(w10, f10.y, ay);
        ax = fmaf(w01, f01.x, ax);
        ay = fmaf(w01, f01.y, ay);
        ax = fmaf(w11, f11.x, ax);
        ay = fmaf(w11, f11.y, ay);

        float vx = wx * ax;
        float vy = wx * ay;

        // sum the two x-halves
        vx += __shfl_xor_sync(0xffffffffu, vx, 1);
        vy += __shfl_xor_sync(0xffffffffu, vy, 1);

        // lane p stashes levels 8p..8p+7
        if ((l >> 3) == (int)p) {
            rf[2 * (l & 7) + 0] = vx;
            rf[2 * (l & 7) + 1] = vy;
        }
    }

    if (valid) {
        float4* o = reinterpret_cast<float4*>(out + (size_t)oidx * 32) + 4 * p;
        o[0] = make_float4(rf[0],  rf[1],  rf[2],  rf[3]);
        o[1] = make_float4(rf[4],  rf[5],  rf[6],  rf[7]);
        o[2] = make_float4(rf[8],  rf[9],  rf[10], rf[11]);
        o[3] = make_float4(rf[12], rf[13], rf[14], rf[15]);
    }
}

extern "C" void kernel_launch(void* const* d_in, const int* in_sizes, int n_in,
                              void* d_out, int out_size)
{
    const float* x      = (const float*)d_in[0];
    const float* tables = (const float*)d_in[1];
    float*       out    = (float*)d_out;
    const int    n      = in_sizes[0] / 3;

    // Replicate the reference's level-resolution math EXACTLY in double precision.
    LP lp;
    const double b = exp((log(512.0) - log(16.0)) / 15.0);
    for (int l = 0; l < NLEV; ++l) {
        const double r   = floor(16.0 * pow(b, (double)l));
        const long   res = (long)r;
        long sz = res * res * res;
        if (sz > (1L << 19)) sz = (1L << 19);
        long p = 1;
        while (p < sz) p <<= 1;
        lp.res[l]  = (float)r;
        lp.mask[l] = (unsigned)(p - 1);
    }

    static void* hist_ptr = nullptr;
    if (!hist_ptr) cudaGetSymbolAddress(&hist_ptr, d_hist);

    // 1) zero histogram (1 MB)
    cudaMemsetAsync(hist_ptr, 0, NBINS * sizeof(unsigned), 0);

    // 2) histogram; cache key + within-bin rank per point
    k_hist<<<(n + 255) / 256, 256>>>(x, n);

    // 3) two-level exclusive scan
    k_scan1<<<NSCANBLKS, 1024>>>();
    k_scan2<<<1, 128>>>();

    // 4) atomic-free scatter of permutation indices
    k_scatter<<<(n + 255) / 256, 256>>>(n);

    // 5) encode: 16 points per warp, 128 points per 256-thread block
    const int threads = 256;
    const int pts_per_block = (threads / 32) * 16;
    const int blocks = (n + pts_per_block - 1) / pts_per_block;
    hashgrid_kernel<<<blocks, threads>>>(x, tables, out, lp, n);
}